// round 15
// baseline (speedup 1.0000x reference)
#include <cuda_runtime.h>
#include <cstdint>

#define B_SZ 1024
#define T_SZ 512
#define F_SZ 124
#define NROWS (B_SZ * T_SZ)

// Pre-activations of layer0, [b][t] as float4 (xyz = hidden, w = pad). 8.4MB -> L2.
__device__ float4 g_pre[NROWS];

extern __shared__ unsigned char dynsmem[];

__device__ __forceinline__ float tanha(float v) {
    float r;
    asm("tanh.approx.f32 %0, %1;" : "=f"(r) : "f"(v));
    return r;
}
__device__ __forceinline__ void cp_async16(unsigned int saddr, const void* gptr) {
    asm volatile("cp.async.cg.shared.global [%0], [%1], 16;" :: "r"(saddr), "l"(gptr));
}
#define CP_COMMIT() asm volatile("cp.async.commit_group;" ::: "memory")
#define CP_WAIT1()  asm volatile("cp.async.wait_group 1;"  ::: "memory")

// ---------------------------------------------------------------------------
// Kernel A: pre[b][t][i] = dot(x[b,t,:], W_ih0[i,:]) + biases.  (unchanged)
// ---------------------------------------------------------------------------
__global__ __launch_bounds__(256) void pre_kernel(
    const float* __restrict__ x,
    const float* __restrict__ Wih0,
    const float* __restrict__ bih0,
    const float* __restrict__ bhh0)
{
    float* s2 = (float*)dynsmem;         // [2][256*36] = 73728 B
    __shared__ float sW[3 * 128];        // W_ih0 zero-padded to 128 cols

    const int tid  = threadIdx.x;
    const int row0 = blockIdx.x * 256;
    const int lane = tid & 31;
    const int lrbase = (tid >> 5) * 32 + (lane >> 3);
    const int c4     = lane & 7;
    const float4* __restrict__ x4 = (const float4*)x;   // row stride 31 float4

#define STAGE_PRE(bufidx, kc, nc4)                                         \
    if (c4 < (nc4)) {                                                      \
        _Pragma("unroll")                                                  \
        for (int it = 0; it < 8; it++) {                                   \
            const int lr = lrbase + it * 4;                                \
            unsigned int sa = (unsigned int)__cvta_generic_to_shared(      \
                &s2[(bufidx) * 9216 + lr * 36 + c4 * 4]);                  \
            cp_async16(sa, &x4[(row0 + lr) * 31 + ((kc) >> 2) + c4]);      \
        }                                                                  \
    }

    STAGE_PRE(0, 0, 8);  CP_COMMIT();
    STAGE_PRE(1, 32, 8); CP_COMMIT();

    for (int idx = tid; idx < 3 * 128; idx += 256) {
        int i = idx >> 7, cc = idx & 127;
        sW[idx] = (cc < F_SZ) ? Wih0[i * F_SZ + cc] : 0.0f;
    }
    const float bs0 = bih0[0] + bhh0[0];
    const float bs1 = bih0[1] + bhh0[1];
    const float bs2 = bih0[2] + bhh0[2];
    __syncthreads();

    float acc0 = 0.f, acc1 = 0.f, acc2 = 0.f;

    #pragma unroll
    for (int ci = 0; ci < 4; ci++) {
        const int kc  = ci * 32;
        const int nc4 = (ci == 3) ? 7 : 8;

        CP_WAIT1();
        __syncwarp();

        const float* sb = &s2[(ci & 1) * 9216];
        #pragma unroll
        for (int cc = 0; cc < 8; cc++) {
            if (cc < nc4) {
                float4 v  = *(const float4*)&sb[tid * 36 + cc * 4];
                float4 w0 = *(const float4*)&sW[0 * 128 + kc + cc * 4];
                float4 w1 = *(const float4*)&sW[1 * 128 + kc + cc * 4];
                float4 w2 = *(const float4*)&sW[2 * 128 + kc + cc * 4];
                acc0 += v.x * w0.x + v.y * w0.y + v.z * w0.z + v.w * w0.w;
                acc1 += v.x * w1.x + v.y * w1.y + v.z * w1.z + v.w * w1.w;
                acc2 += v.x * w2.x + v.y * w2.y + v.z * w2.z + v.w * w2.w;
            }
        }
        __syncwarp();

        if (ci < 2) {
            const int kn = (ci + 2) * 32;
            const int nn = (ci + 2 == 3) ? 7 : 8;
            STAGE_PRE(ci & 1, kn, nn);
        }
        CP_COMMIT();
    }

    g_pre[row0 + tid] = make_float4(acc0 + bs0, acc1 + bs1, acc2 + bs2, 0.0f);
}
#undef STAGE_PRE

// ---------------------------------------------------------------------------
// Kernel B: layer-split v2. 32 blocks x 64 threads.
//   Warp A (lanes 0-31):  layer-0 recurrence + the h1-INDEPENDENT part of
//     layer 1:  S(s) = C·n0(s) + bb.  Ships S through sRing.
//     Per step: 18 FFMA + 3 TANH.  Recurrent chain: 3 FFMA + tanh = 28 cyc.
//   Warp B (lanes 32-63): layer-1 D-part only: h1 = tanh(D·h1 + S), + fc.
//     Per step: 9 FFMA + 3 TANH.   Recurrent chain: 3 FFMA + tanh = 28 cyc.
//   Different SMSPs -> separate MUFU pipes: per-warp tanh load halved (the
//   R12 kernel was pinned at 6 tanh/step/warp ~= its MUFU floor).
// One __syncthreads per 32-step chunk; B's ring loads & S have no h1 dep.
// ---------------------------------------------------------------------------
#define CH    32
#define NST   3
#define NCHK  (T_SZ / CH)               // 16

__global__ __launch_bounds__(64) void rnn_kernel(
    const float* __restrict__ Whh0,
    const float* __restrict__ Wih1,
    const float* __restrict__ Whh1,
    const float* __restrict__ bih1,
    const float* __restrict__ bhh1,
    const float* __restrict__ Wfc,
    const float* __restrict__ bfc,
    float* __restrict__ out)
{
    // preRing [NST][CH][32] (48KB) then sRing [2][CH][32] (32KB)
    float4* preRing = (float4*)dynsmem;
    float4* sRing   = preRing + NST * CH * 32;

    const int tid  = threadIdx.x;
    const int lane = tid & 31;
    const bool isA = (tid < 32);
    const int b    = blockIdx.x * 32 + lane;
    const float4* __restrict__ gsrc = g_pre + (size_t)b * T_SZ;

    // ---- warp A state ----
    float a0=0,a1=0,a2=0,a3=0,a4=0,a5=0,a6=0,a7=0,a8=0;     // Whh0
    float c0=0,c1=0,c2=0,c3=0,c4=0,c5=0,c6=0,c7=0,c8=0;     // Wih1
    float bb0=0, bb1=0, bb2=0;
    float n0x=0.f, n0y=0.f, n0z=0.f;
    // ---- warp B state ----
    float d0=0,d1=0,d2=0,d3=0,d4=0,d5=0,d6=0,d7=0,d8=0;     // Whh1
    float h1x=0.f, h1y=0.f, h1z=0.f;

    if (isA) {
        a0=Whh0[0]; a1=Whh0[1]; a2=Whh0[2];
        a3=Whh0[3]; a4=Whh0[4]; a5=Whh0[5];
        a6=Whh0[6]; a7=Whh0[7]; a8=Whh0[8];
        c0=Wih1[0]; c1=Wih1[1]; c2=Wih1[2];
        c3=Wih1[3]; c4=Wih1[4]; c5=Wih1[5];
        c6=Wih1[6]; c7=Wih1[7]; c8=Wih1[8];
        bb0 = bih1[0] + bhh1[0];
        bb1 = bih1[1] + bhh1[1];
        bb2 = bih1[2] + bhh1[2];
        // prologue: pre chunks 0,1 in flight
        #pragma unroll
        for (int c = 0; c < 2; c++) {
            #pragma unroll
            for (int s = 0; s < CH; s++) {
                unsigned int sa = (unsigned int)__cvta_generic_to_shared(
                    &preRing[(c * CH + s) * 32 + lane]);
                cp_async16(sa, gsrc + c * CH + s);
            }
            CP_COMMIT();
        }
    } else {
        d0=Whh1[0]; d1=Whh1[1]; d2=Whh1[2];
        d3=Whh1[3]; d4=Whh1[4]; d5=Whh1[5];
        d6=Whh1[6]; d7=Whh1[7]; d8=Whh1[8];
    }

    for (int c = 0; c <= NCHK; c++) {
        if (isA && c < NCHK) CP_WAIT1();     // pre chunk c landed (A staged, A reads)
        __syncthreads();                     // publish sRing chunk c-1; recycle bufs

        if (isA) {
            if (c < NCHK) {
                // stage pre chunk c+2 first so L2 traffic overlaps math
                const int cn = c + 2;
                if (cn < NCHK) {
                    const int st = cn % NST;
                    #pragma unroll
                    for (int s = 0; s < CH; s++) {
                        unsigned int sa = (unsigned int)__cvta_generic_to_shared(
                            &preRing[(st * CH + s) * 32 + lane]);
                        cp_async16(sa, gsrc + cn * CH + s);
                    }
                }
                CP_COMMIT();                 // possibly-empty; keeps wait counts aligned

                const float4* pr = &preRing[(c % NST) * CH * 32];
                float4*       sw = &sRing[(c & 1) * CH * 32];
                #pragma unroll
                for (int s = 0; s < CH; s++) {
                    const float4 p = pr[s * 32 + lane];
                    // L0: recurrent chain = 3 FFMA + tanh
                    const float m0 = fmaf(a0, n0x, fmaf(a1, n0y, fmaf(a2, n0z, p.x)));
                    const float m1 = fmaf(a3, n0x, fmaf(a4, n0y, fmaf(a5, n0z, p.y)));
                    const float m2 = fmaf(a6, n0x, fmaf(a7, n0y, fmaf(a8, n0z, p.z)));
                    n0x = tanha(m0); n0y = tanha(m1); n0z = tanha(m2);
                    // h1-independent L1 part (off A's chain)
                    const float S0 = fmaf(c0, n0x, fmaf(c1, n0y, fmaf(c2, n0z, bb0)));
                    const float S1 = fmaf(c3, n0x, fmaf(c4, n0y, fmaf(c5, n0z, bb1)));
                    const float S2 = fmaf(c6, n0x, fmaf(c7, n0y, fmaf(c8, n0z, bb2)));
                    sw[s * 32 + lane] = make_float4(S0, S1, S2, 0.f);
                }
            }
        } else if (c >= 1) {
            const float4* sr = &sRing[((c - 1) & 1) * CH * 32];
            #pragma unroll
            for (int s = 0; s < CH; s++) {
                const float4 S = sr[s * 32 + lane];   // no h1 dep -> hoistable
                const float t0 = fmaf(d0, h1x, fmaf(d1, h1y, fmaf(d2, h1z, S.x)));
                const float t1 = fmaf(d3, h1x, fmaf(d4, h1y, fmaf(d5, h1z, S.y)));
                const float t2 = fmaf(d6, h1x, fmaf(d7, h1y, fmaf(d8, h1z, S.z)));
                h1x = tanha(t0); h1y = tanha(t1); h1z = tanha(t2);
            }
        }
    }

    if (!isA) {
        #pragma unroll
        for (int o = 0; o < 6; o++) {
            out[b * 6 + o] = bfc[o] + Wfc[o * 3 + 0] * h1x
                                    + Wfc[o * 3 + 1] * h1y
                                    + Wfc[o * 3 + 2] * h1z;
        }
    }
}

extern "C" void kernel_launch(void* const* d_in, const int* in_sizes, int n_in,
                              void* d_out, int out_size)
{
    (void)in_sizes; (void)n_in; (void)out_size;
    const float* x    = (const float*)d_in[0];
    const float* Wih0 = (const float*)d_in[1];
    const float* Whh0 = (const float*)d_in[2];
    const float* bih0 = (const float*)d_in[3];
    const float* bhh0 = (const float*)d_in[4];
    const float* Wih1 = (const float*)d_in[5];
    const float* Whh1 = (const float*)d_in[6];
    const float* bih1 = (const float*)d_in[7];
    const float* bhh1 = (const float*)d_in[8];
    const float* Wfc  = (const float*)d_in[9];
    const float* bfc  = (const float*)d_in[10];
    float* out = (float*)d_out;

    const int pre_smem = 2 * 256 * 36 * sizeof(float);                 // 73728 B
    const int rnn_smem = (NST + 2) * CH * 32 * (int)sizeof(float4);    // 81920 B
    cudaFuncSetAttribute(pre_kernel, cudaFuncAttributeMaxDynamicSharedMemorySize, pre_smem);
    cudaFuncSetAttribute(rnn_kernel, cudaFuncAttributeMaxDynamicSharedMemorySize, rnn_smem);

    pre_kernel<<<NROWS / 256, 256, pre_smem>>>(x, Wih0, bih0, bhh0);
    rnn_kernel<<<B_SZ / 32, 64, rnn_smem>>>(Whh0, Wih1, Whh1, bih1, bhh1, Wfc, bfc, out);
}

// round 16
// speedup vs baseline: 1.4521x; 1.4521x over previous
#include <cuda_runtime.h>
#include <cstdint>

#define B_SZ 1024
#define T_SZ 512
#define F_SZ 124
#define NROWS (B_SZ * T_SZ)

#define NSLICE 16
#define TSLICE 32                               // timesteps per slice
#define BPB    8                                // batch elems per pre block
#define BLKS_PER_SLICE (B_SZ / BPB)             // 128
#define PRE_BLOCKS (NSLICE * BLKS_PER_SLICE)    // 2048
#define RNN_BLOCKS (B_SZ / 32)                  // 32
#define GRID_SZ (PRE_BLOCKS + RNN_BLOCKS)

// Pre-activations of layer0, [b][t] as float4 (xyz = hidden, w = pad). 8.4MB -> L2.
__device__ float4 g_pre[NROWS];
// Per-slice completion counters (reset by zero_prog each launch).
__device__ int g_prog[NSLICE];

extern __shared__ unsigned char dynsmem[];

__device__ __forceinline__ float tanha(float v) {
    float r;
    asm("tanh.approx.f32 %0, %1;" : "=f"(r) : "f"(v));
    return r;
}
__device__ __forceinline__ void cp_async16(unsigned int saddr, const void* gptr) {
    asm volatile("cp.async.cg.shared.global [%0], [%1], 16;" :: "r"(saddr), "l"(gptr));
}
#define CP_COMMIT() asm volatile("cp.async.commit_group;" ::: "memory")
#define CP_WAIT1()  asm volatile("cp.async.wait_group 1;"  ::: "memory")

__device__ __forceinline__ void spin_slice(int j) {
    // all lanes poll the same address (broadcast load); writer did fence+atomic release
    for (;;) {
        int v;
        asm volatile("ld.acquire.gpu.b32 %0, [%1];" : "=r"(v) : "l"(&g_prog[j]));
        if (v >= BLKS_PER_SLICE) return;
        __nanosleep(128);
    }
}

__global__ void zero_prog() {
    if (threadIdx.x < NSLICE) g_prog[threadIdx.x] = 0;
}

// ---------------------------------------------------------------------------
// Fused kernel.
//   blocks [0, 32):        rnn consumers — one warp, one batch elem per lane,
//                          R12 dual-dataflow body (proven 98 cyc/step floor),
//                          spin on g_prog[slice] before staging each chunk.
//   blocks [32, 32+2048):  pre producers — slice-major: slice j = timesteps
//                          [32j, 32j+32) for 8 batch elems per block; signals
//                          g_prog[j] when done. DRAM-bound, cp.async pipelined.
// rnn blocks come FIRST so wave-1 scheduling co-residents them with pre.
// ---------------------------------------------------------------------------
#define CH    32                      // rnn chunk = one slice
#define NST   3
#define NCHK  NSLICE                  // 16

__global__ __launch_bounds__(256) void fused_kernel(
    const float* __restrict__ x,
    const float* __restrict__ Wih0,
    const float* __restrict__ bih0,
    const float* __restrict__ bhh0,
    const float* __restrict__ Whh0,
    const float* __restrict__ Wih1,
    const float* __restrict__ Whh1,
    const float* __restrict__ bih1,
    const float* __restrict__ bhh1,
    const float* __restrict__ Wfc,
    const float* __restrict__ bfc,
    float* __restrict__ out)
{
    const int tid = threadIdx.x;

    if (blockIdx.x < RNN_BLOCKS) {
        // ================= RNN path (1 warp) =================
        if (tid >= 32) return;
        float4* ring = (float4*)dynsmem;          // [NST][CH][32] = 48KB

        const int lane = tid;
        const int b    = blockIdx.x * 32 + lane;
        const float4* __restrict__ gsrc = g_pre + (size_t)b * T_SZ;

        const float a0 = Whh0[0], a1 = Whh0[1], a2 = Whh0[2];
        const float a3 = Whh0[3], a4 = Whh0[4], a5 = Whh0[5];
        const float a6 = Whh0[6], a7 = Whh0[7], a8 = Whh0[8];
        const float c0 = Wih1[0], c1 = Wih1[1], c2 = Wih1[2];
        const float c3 = Wih1[3], c4 = Wih1[4], c5 = Wih1[5];
        const float c6 = Wih1[6], c7 = Wih1[7], c8 = Wih1[8];
        const float d0 = Whh1[0], d1 = Whh1[1], d2 = Whh1[2];
        const float d3 = Whh1[3], d4 = Whh1[4], d5 = Whh1[5];
        const float d6 = Whh1[6], d7 = Whh1[7], d8 = Whh1[8];
        const float bb0 = bih1[0] + bhh1[0];
        const float bb1 = bih1[1] + bhh1[1];
        const float bb2 = bih1[2] + bhh1[2];

        float n0x = 0.f, n0y = 0.f, n0z = 0.f;     // layer-0 state
        float h1x = 0.f, h1y = 0.f, h1z = 0.f;     // layer-1 state

#define L1_PREV()                                                          \
    {                                                                      \
        const float S0 = fmaf(c0, n0x, fmaf(c1, n0y, fmaf(c2, n0z, bb0))); \
        const float S1 = fmaf(c3, n0x, fmaf(c4, n0y, fmaf(c5, n0z, bb1))); \
        const float S2 = fmaf(c6, n0x, fmaf(c7, n0y, fmaf(c8, n0z, bb2))); \
        const float t0 = fmaf(d0, h1x, fmaf(d1, h1y, fmaf(d2, h1z, S0)));  \
        const float t1 = fmaf(d3, h1x, fmaf(d4, h1y, fmaf(d5, h1z, S1)));  \
        const float t2 = fmaf(d6, h1x, fmaf(d7, h1y, fmaf(d8, h1z, S2)));  \
        h1x = tanha(t0); h1y = tanha(t1); h1z = tanha(t2);                 \
    }
#define L0_CUR(p)                                                          \
    {                                                                      \
        const float m0 = fmaf(a0, n0x, fmaf(a1, n0y, fmaf(a2, n0z, (p).x))); \
        const float m1 = fmaf(a3, n0x, fmaf(a4, n0y, fmaf(a5, n0z, (p).y))); \
        const float m2 = fmaf(a6, n0x, fmaf(a7, n0y, fmaf(a8, n0z, (p).z))); \
        n0x = tanha(m0); n0y = tanha(m1); n0z = tanha(m2);                 \
    }
#define STAGE_CHUNK(cc)                                                    \
    {                                                                      \
        const int st_ = (cc) % NST;                                        \
        _Pragma("unroll")                                                  \
        for (int s_ = 0; s_ < CH; s_++) {                                  \
            unsigned int sa_ = (unsigned int)__cvta_generic_to_shared(     \
                &ring[(st_ * CH + s_) * 32 + lane]);                       \
            cp_async16(sa_, gsrc + (cc) * CH + s_);                        \
        }                                                                  \
    }

        // prologue: wait for slices 0,1 then put both chunks in flight
        spin_slice(0); STAGE_CHUNK(0); CP_COMMIT();
        spin_slice(1); STAGE_CHUNK(1); CP_COMMIT();

        for (int c = 0; c < NCHK; c++) {
            CP_WAIT1();                           // chunk c landed (self-staged)
            const float4* pr = &ring[(c % NST) * CH * 32];

            if (c == 0) {                         // peel step 0 (no L1 yet)
                { const float4 p = pr[0 * 32 + lane]; L0_CUR(p); }
                #pragma unroll
                for (int s = 1; s < CH; s++) {
                    const float4 p = pr[s * 32 + lane];
                    L1_PREV();
                    L0_CUR(p);
                }
            } else {
                #pragma unroll
                for (int s = 0; s < CH; s++) {
                    const float4 p = pr[s * 32 + lane];
                    L1_PREV();
                    L0_CUR(p);
                }
            }

            const int cn = c + 2;                 // stage after compute: spin
            if (cn < NCHK) {                      // mustn't delay this chunk
                spin_slice(cn);
                STAGE_CHUNK(cn);
            }
            CP_COMMIT();                          // keeps group counts aligned
        }

        L1_PREV();                                // L1 for final step

#undef L1_PREV
#undef L0_CUR
#undef STAGE_CHUNK

        #pragma unroll
        for (int o = 0; o < 6; o++) {
            out[b * 6 + o] = bfc[o] + Wfc[o * 3 + 0] * h1x
                                    + Wfc[o * 3 + 1] * h1y
                                    + Wfc[o * 3 + 2] * h1z;
        }
        return;
    }

    // ================= PRE path =================
    // block p: slice = p>>7 (timesteps [32*slice, +32)), b0 = (p&127)*8.
    // Warp w handles batch elem b0+w, all 32 timesteps (256 rows per block).
    {
        float* s2 = (float*)dynsmem;              // [2][256*36] = 73728 B
        __shared__ float sW[3 * 128];

        const int p     = blockIdx.x - RNN_BLOCKS;
        const int slice = p >> 7;
        const int b0    = (p & 127) * BPB;
        const int t0    = slice * TSLICE;

        const int lane = tid & 31;
        const int w    = tid >> 5;
        const int c4   = lane & 7;
        const float4* __restrict__ x4 = (const float4*)x;   // row stride 31 float4
        // global row for staging iteration 'it': (b0+w)*512 + t0 + (lane>>3) + it*4
        const long grow_base = (long)(b0 + w) * T_SZ + t0 + (lane >> 3);
        // local smem row for 'it': w*32 + (lane>>3) + it*4

#define STAGE_PRE(bufidx, kc, nc4)                                         \
    if (c4 < (nc4)) {                                                      \
        _Pragma("unroll")                                                  \
        for (int it = 0; it < 8; it++) {                                   \
            const int lr = w * 32 + (lane >> 3) + it * 4;                  \
            unsigned int sa = (unsigned int)__cvta_generic_to_shared(      \
                &s2[(bufidx) * 9216 + lr * 36 + c4 * 4]);                  \
            cp_async16(sa, &x4[(grow_base + it * 4) * 31 + ((kc) >> 2) + c4]); \
        }                                                                  \
    }

        STAGE_PRE(0, 0, 8);  CP_COMMIT();
        STAGE_PRE(1, 32, 8); CP_COMMIT();

        for (int idx = tid; idx < 3 * 128; idx += 256) {
            int i = idx >> 7, cc = idx & 127;
            sW[idx] = (cc < F_SZ) ? Wih0[i * F_SZ + cc] : 0.0f;
        }
        const float bs0 = bih0[0] + bhh0[0];
        const float bs1 = bih0[1] + bhh0[1];
        const float bs2 = bih0[2] + bhh0[2];
        __syncthreads();

        float acc0 = 0.f, acc1 = 0.f, acc2 = 0.f;

        #pragma unroll
        for (int ci = 0; ci < 4; ci++) {
            const int kc  = ci * 32;
            const int nc4 = (ci == 3) ? 7 : 8;

            CP_WAIT1();
            __syncwarp();

            const float* sb = &s2[(ci & 1) * 9216];
            #pragma unroll
            for (int cc = 0; cc < 8; cc++) {
                if (cc < nc4) {
                    float4 v  = *(const float4*)&sb[tid * 36 + cc * 4];
                    float4 w0 = *(const float4*)&sW[0 * 128 + kc + cc * 4];
                    float4 w1 = *(const float4*)&sW[1 * 128 + kc + cc * 4];
                    float4 w2 = *(const float4*)&sW[2 * 128 + kc + cc * 4];
                    acc0 += v.x * w0.x + v.y * w0.y + v.z * w0.z + v.w * w0.w;
                    acc1 += v.x * w1.x + v.y * w1.y + v.z * w1.z + v.w * w1.w;
                    acc2 += v.x * w2.x + v.y * w2.y + v.z * w2.z + v.w * w2.w;
                }
            }
            __syncwarp();

            if (ci < 2) {
                const int kn = (ci + 2) * 32;
                const int nn = (ci + 2 == 3) ? 7 : 8;
                STAGE_PRE(ci & 1, kn, nn);
            }
            CP_COMMIT();
        }
#undef STAGE_PRE

        // thread tid -> (b0 + (tid>>5), t0 + (tid&31)); contiguous per warp
        const long orow = (long)(b0 + w) * T_SZ + t0 + (tid & 31);
        g_pre[orow] = make_float4(acc0 + bs0, acc1 + bs1, acc2 + bs2, 0.0f);

        __syncthreads();                          // all block writes done
        if (tid == 0) {
            __threadfence();                      // release: g_pre before counter
            atomicAdd(&g_prog[slice], 1);
        }
    }
}

extern "C" void kernel_launch(void* const* d_in, const int* in_sizes, int n_in,
                              void* d_out, int out_size)
{
    (void)in_sizes; (void)n_in; (void)out_size;
    const float* x    = (const float*)d_in[0];
    const float* Wih0 = (const float*)d_in[1];
    const float* Whh0 = (const float*)d_in[2];
    const float* bih0 = (const float*)d_in[3];
    const float* bhh0 = (const float*)d_in[4];
    const float* Wih1 = (const float*)d_in[5];
    const float* Whh1 = (const float*)d_in[6];
    const float* bih1 = (const float*)d_in[7];
    const float* bhh1 = (const float*)d_in[8];
    const float* Wfc  = (const float*)d_in[9];
    const float* bfc  = (const float*)d_in[10];
    float* out = (float*)d_out;

    const int smem = 2 * 256 * 36 * sizeof(float);   // 73728 B (rnn uses 48KB of it)
    cudaFuncSetAttribute(fused_kernel, cudaFuncAttributeMaxDynamicSharedMemorySize, smem);

    zero_prog<<<1, 32>>>();
    fused_kernel<<<GRID_SZ, 256, smem>>>(x, Wih0, bih0, bhh0,
                                         Whh0, Wih1, Whh1, bih1, bhh1,
                                         Wfc, bfc, out);
}